// round 1
// baseline (speedup 1.0000x reference)
#include <cuda_runtime.h>
#include <cuda_bf16.h>
#include <math.h>

#define N_NODES 50000
#define N_EDGES 800000
#define NFEAT 128
#define NHID 96
#define NCLASS 64
#define NEXT 32
#define BN_EPS 1e-5f

// ---------------- scratch (device globals; no allocations allowed) ----------
__device__ float g_support1[N_NODES * NHID];    // x @ W1
__device__ float g_agg1[N_NODES * NHID];        // spmm result / h1 (in-place selu)
__device__ float g_support2[N_NODES * NCLASS];  // h1 @ W2
__device__ float g_agg2[N_NODES * NCLASS];      // spmm2 result
__device__ float g_pool[NCLASS];                // column sums of selu(agg2+b2)

// ---------------- helpers ----------------------------------------------------
__device__ __forceinline__ float selu_f(float v) {
    const float scale = 1.0507009873554805f;
    const float alpha = 1.6732632423543772f;
    return scale * (v > 0.0f ? v : alpha * (expf(v) - 1.0f));
}

__device__ __forceinline__ void red_add_v4(float* addr, float4 v) {
    asm volatile("red.global.add.v4.f32 [%0], {%1, %2, %3, %4};"
                 :: "l"(addr), "f"(v.x), "f"(v.y), "f"(v.z), "f"(v.w)
                 : "memory");
}

// ---------------- zero scratch (runs every replay; graph-capturable) ---------
__global__ void zero_kernel() {
    int i = blockIdx.x * blockDim.x + threadIdx.x;
    float4 z = make_float4(0.f, 0.f, 0.f, 0.f);
    if (i < N_NODES * (NHID / 4))   reinterpret_cast<float4*>(g_agg1)[i] = z;
    if (i < N_NODES * (NCLASS / 4)) reinterpret_cast<float4*>(g_agg2)[i] = z;
    if (i < NCLASS / 4)             reinterpret_cast<float4*>(g_pool)[i] = z;
}

// ---------------- tiled fp32 GEMM: C[M,N] = A[M,K] @ W[K,N] ------------------
// BM=64, BK=32, 256 threads as 16x16, microtile TM=4 x TN=N/16.
template <int K, int N, int TN>
__global__ __launch_bounds__(256)
void gemm_kernel(const float* __restrict__ A, const float* __restrict__ W,
                 float* __restrict__ C, int M) {
    constexpr int BM = 64, BK = 32, TM = 4;
    __shared__ float As[BK][BM + 1];   // +1 pad: conflict-free stores
    __shared__ float Ws[BK][N];

    const int t  = threadIdx.x;
    const int tx = t % 16;       // column group
    const int ty = t / 16;       // row group
    const int m0 = blockIdx.x * BM;

    float acc[TM][TN];
#pragma unroll
    for (int i = 0; i < TM; i++)
#pragma unroll
        for (int j = 0; j < TN; j++) acc[i][j] = 0.f;

    for (int kk = 0; kk < K; kk += BK) {
        // load A tile (BM*BK = 2048 elems, 8 per thread, coalesced along k)
#pragma unroll
        for (int r = 0; r < (BM * BK) / 256; r++) {
            int i = t + r * 256;
            int m = i >> 5;        // /BK
            int k = i & 31;        // %BK
            float v = 0.f;
            if (m0 + m < M) v = A[(size_t)(m0 + m) * K + kk + k];
            As[k][m] = v;
        }
        // load W tile (BK*N elems, coalesced along j)
#pragma unroll
        for (int r = 0; r < (BK * N) / 256; r++) {
            int i = t + r * 256;
            int k = i / N;
            int j = i % N;
            Ws[k][j] = W[(size_t)(kk + k) * N + j];
        }
        __syncthreads();

#pragma unroll
        for (int k = 0; k < BK; k++) {
            float a[TM], b[TN];
#pragma unroll
            for (int i = 0; i < TM; i++) a[i] = As[k][ty * TM + i];
#pragma unroll
            for (int j = 0; j < TN; j++) b[j] = Ws[k][tx * TN + j];
#pragma unroll
            for (int i = 0; i < TM; i++)
#pragma unroll
                for (int j = 0; j < TN; j++) acc[i][j] += a[i] * b[j];
        }
        __syncthreads();
    }

#pragma unroll
    for (int i = 0; i < TM; i++) {
        int m = m0 + ty * TM + i;
        if (m < M) {
#pragma unroll
            for (int j = 0; j < TN; j++)
                C[(size_t)m * N + tx * TN + j] = acc[i][j];
        }
    }
}

// ---------------- SpMM: agg[row[e]] += w[e] * support[col[e]] ---------------
// CH = floats-per-row / 4. Threads of a warp cover consecutive float4 chunks of
// the same edge -> contiguous 128B+ gathers/scatters in L2.
template <int CH, int TPB>
__global__ __launch_bounds__(TPB)
void spmm_kernel(const int* __restrict__ row, const int* __restrict__ col,
                 const float* __restrict__ ew,
                 const float4* __restrict__ sup, float* __restrict__ agg,
                 int E) {
    int idx = blockIdx.x * TPB + threadIdx.x;
    int e = idx / CH;
    int c = idx - e * CH;
    if (e >= E) return;
    int r  = row[e];
    int cl = col[e];
    float w = ew[e];
    float4 v = sup[(size_t)cl * CH + c];
    v.x *= w; v.y *= w; v.z *= w; v.w *= w;
    red_add_v4(agg + ((size_t)r * CH + c) * 4, v);
}

// ---------------- layer-1 epilogue: h1 = selu(agg1 + b1), in place ----------
__global__ __launch_bounds__(256)
void bias_selu1_kernel(const float* __restrict__ b1) {
    int i = blockIdx.x * blockDim.x + threadIdx.x;
    const int TOT = N_NODES * (NHID / 4);
    if (i >= TOT) return;
    int c = i % (NHID / 4);
    int j = c * 4;
    float4 v = reinterpret_cast<float4*>(g_agg1)[i];
    v.x = selu_f(v.x + b1[j + 0]);
    v.y = selu_f(v.y + b1[j + 1]);
    v.z = selu_f(v.z + b1[j + 2]);
    v.w = selu_f(v.w + b1[j + 3]);
    reinterpret_cast<float4*>(g_agg1)[i] = v;
}

// ---------------- layer-2 epilogue fused with mean-pool ----------------------
// h2 is only consumed by the mean -> never materialized. Block handles 128
// nodes; per-column partials reduced in smem, one atomicAdd per column/block.
__global__ __launch_bounds__(256)
void selu_pool_kernel(const float* __restrict__ b2) {
    __shared__ float s[256];
    int t = threadIdx.x;
    int j = t & 63;       // column 0..63
    int g = t >> 6;       // node sub-group 0..3
    int base = blockIdx.x * 128;
    int nend = base + 128;
    if (nend > N_NODES) nend = N_NODES;
    float bj = b2[j];
    float acc = 0.f;
    for (int n = base + g; n < nend; n += 4)
        acc += selu_f(g_agg2[(size_t)n * NCLASS + j] + bj);
    s[t] = acc;
    __syncthreads();
    if (t < 64) {
        float sum = s[t] + s[t + 64] + s[t + 128] + s[t + 192];
        atomicAdd(&g_pool[t], sum);
    }
}

// ---------------- final head: BN, concat, FC, log-softmax, L1 ----------------
__global__ __launch_bounds__(128)
void final_kernel(const float* __restrict__ sub, const float* __restrict__ Wf,
                  const float* __restrict__ bf, const float* __restrict__ gamma,
                  const float* __restrict__ beta, const float* __restrict__ mean,
                  const float* __restrict__ var, float* __restrict__ out) {
    __shared__ float z[NCLASS + NEXT];
    __shared__ float logits[NCLASS];
    __shared__ float red[128];
    __shared__ float s_max, s_lse;
    int t = threadIdx.x;

    if (t < NCLASS) {
        z[t] = selu_f(g_pool[t] / (float)N_NODES);
    } else if (t < NCLASS + NEXT) {
        int j = t - NCLASS;
        z[t] = (sub[j] - mean[j]) * rsqrtf(var[j] + BN_EPS) * gamma[j] + beta[j];
    }
    __syncthreads();

    if (t < NCLASS) {
        float a = bf[t];
        const float* wrow = Wf + (size_t)t * (NCLASS + NEXT);
#pragma unroll
        for (int k = 0; k < NCLASS + NEXT; k++) a += z[k] * wrow[k];
        logits[t] = a;
    }
    __syncthreads();

    if (t == 0) {
        float m = -INFINITY;
        for (int k = 0; k < NCLASS; k++) m = fmaxf(m, logits[k]);
        float s = 0.f;
        for (int k = 0; k < NCLASS; k++) s += expf(logits[k] - m);
        s_max = m;
        s_lse = logf(s);
    }
    __syncthreads();
    if (t < NCLASS) out[t] = logits[t] - s_max - s_lse;

    // L1 over Wf (64*96 = 6144 elements)
    float l = 0.f;
    const int TOTW = NCLASS * (NCLASS + NEXT);
    for (int i = t; i < TOTW; i += 128) l += fabsf(Wf[i]);
    red[t] = l;
    __syncthreads();
    for (int s2 = 64; s2 > 0; s2 >>= 1) {
        if (t < s2) red[t] += red[t + s2];
        __syncthreads();
    }
    if (t == 0) out[NCLASS] = red[0] / (float)TOTW;
}

// ---------------- launch -----------------------------------------------------
extern "C" void kernel_launch(void* const* d_in, const int* in_sizes, int n_in,
                              void* d_out, int out_size) {
    const float* x     = (const float*)d_in[0];
    const int*   row   = (const int*)  d_in[1];
    const int*   col   = (const int*)  d_in[2];
    const float* ew    = (const float*)d_in[3];
    const float* sub   = (const float*)d_in[4];
    const float* W1    = (const float*)d_in[5];
    const float* b1    = (const float*)d_in[6];
    const float* W2    = (const float*)d_in[7];
    const float* b2    = (const float*)d_in[8];
    const float* Wf    = (const float*)d_in[9];
    const float* bf    = (const float*)d_in[10];
    const float* gamma = (const float*)d_in[11];
    const float* beta  = (const float*)d_in[12];
    const float* mean  = (const float*)d_in[13];
    const float* var   = (const float*)d_in[14];
    float* out = (float*)d_out;

    const int M = N_NODES;
    const int E = (n_in > 1) ? in_sizes[1] : N_EDGES;

    void *p_sup1, *p_agg1, *p_sup2, *p_agg2;
    cudaGetSymbolAddress(&p_sup1, g_support1);
    cudaGetSymbolAddress(&p_agg1, g_agg1);
    cudaGetSymbolAddress(&p_sup2, g_support2);
    cudaGetSymbolAddress(&p_agg2, g_agg2);

    // zero accumulators (every replay)
    {
        int tot = N_NODES * (NHID / 4);
        zero_kernel<<<(tot + 255) / 256, 256>>>();
    }

    // layer 1: support1 = x @ W1
    gemm_kernel<NFEAT, NHID, 6><<<(M + 63) / 64, 256>>>(x, W1, (float*)p_sup1, M);
    // spmm1: agg1 += A * support1   (CH = 96/4 = 24, 192 threads = 8 edges/blk)
    {
        int total = E * (NHID / 4);
        spmm_kernel<NHID / 4, 192><<<(total + 191) / 192, 192>>>(
            row, col, ew, (const float4*)p_sup1, (float*)p_agg1, E);
    }
    // h1 = selu(agg1 + b1) in place
    {
        int tot = N_NODES * (NHID / 4);
        bias_selu1_kernel<<<(tot + 255) / 256, 256>>>(b1);
    }
    // layer 2: support2 = h1 @ W2
    gemm_kernel<NHID, NCLASS, 4><<<(M + 63) / 64, 256>>>((const float*)p_agg1, W2,
                                                         (float*)p_sup2, M);
    // spmm2 (CH = 64/4 = 16, 256 threads = 16 edges/blk)
    {
        int total = E * (NCLASS / 4);
        spmm_kernel<NCLASS / 4, 256><<<(total + 255) / 256, 256>>>(
            row, col, ew, (const float4*)p_sup2, (float*)p_agg2, E);
    }
    // fused bias+selu+mean-pool (h2 never materialized)
    selu_pool_kernel<<<(N_NODES + 127) / 128, 256>>>(b2);
    // head
    final_kernel<<<1, 128>>>(sub, Wf, bf, gamma, beta, mean, var, out);
}

// round 3
// speedup vs baseline: 1.2899x; 1.2899x over previous
#include <cuda_runtime.h>
#include <cuda_bf16.h>
#include <math.h>

#define N_NODES 50000
#define N_EDGES 800000
#define NFEAT 128
#define NHID 96
#define NCLASS 64
#define NEXT 32
#define BN_EPS 1e-5f

#define SCAN_B 512
#define NB_SCAN ((N_NODES + SCAN_B - 1) / SCAN_B)   // 98

// ---------------- scratch (device globals; no allocations allowed) ----------
__device__ float g_support1[N_NODES * NHID];    // x @ W1
__device__ float g_h1[N_NODES * NHID];          // selu(agg1 + b1)
__device__ float g_support2[N_NODES * NCLASS];  // h1 @ W2
__device__ float g_pool[NCLASS];                // column sums of selu(agg2+b2)

__device__ int  g_cnt[N_NODES];                 // degree (by row)
__device__ int  g_off[N_NODES];                 // CSR offsets
__device__ int  g_cur[N_NODES];                 // scatter cursors
__device__ int  g_partial[NB_SCAN];             // scan block partials
__device__ int2 g_es[N_EDGES];                  // packed (col, w) sorted by row

// ---------------- helpers ----------------------------------------------------
__device__ __forceinline__ float selu_f(float v) {
    const float scale = 1.0507009873554805f;
    const float alpha = 1.6732632423543772f;
    return scale * (v > 0.0f ? v : alpha * (expf(v) - 1.0f));
}

// ---------------- CSR build --------------------------------------------------
__global__ void zero_small_kernel() {
    int i = blockIdx.x * blockDim.x + threadIdx.x;
    if (i < N_NODES) g_cnt[i] = 0;
    if (i < NCLASS)  g_pool[i] = 0.f;
}

__global__ void hist_kernel(const int* __restrict__ row, int E) {
    int e = blockIdx.x * blockDim.x + threadIdx.x;
    if (e < E) atomicAdd(&g_cnt[row[e]], 1);
}

__global__ __launch_bounds__(SCAN_B)
void scanA_kernel() {
    __shared__ int s[SCAN_B];
    int t = threadIdx.x, b = blockIdx.x;
    int i = b * SCAN_B + t;
    int v = (i < N_NODES) ? g_cnt[i] : 0;
    s[t] = v;
    __syncthreads();
    for (int d = 1; d < SCAN_B; d <<= 1) {
        int x = (t >= d) ? s[t - d] : 0;
        __syncthreads();
        s[t] += x;
        __syncthreads();
    }
    if (i < N_NODES) g_off[i] = s[t] - v;        // exclusive within block
    if (t == SCAN_B - 1) g_partial[b] = s[t];    // block total
}

__global__ __launch_bounds__(128)
void scanTop_kernel() {
    __shared__ int s[128];
    int t = threadIdx.x;
    int v = (t < NB_SCAN) ? g_partial[t] : 0;
    s[t] = v;
    __syncthreads();
    for (int d = 1; d < 128; d <<= 1) {
        int x = (t >= d) ? s[t - d] : 0;
        __syncthreads();
        s[t] += x;
        __syncthreads();
    }
    if (t < NB_SCAN) g_partial[t] = s[t] - v;    // exclusive block base
}

__global__ void scanC_kernel() {
    int i = blockIdx.x * blockDim.x + threadIdx.x;
    if (i < N_NODES) {
        int o = g_off[i] + g_partial[i / SCAN_B];
        g_off[i] = o;
        g_cur[i] = o;
    }
}

__global__ void scatter_kernel(const int* __restrict__ row,
                               const int* __restrict__ col,
                               const float* __restrict__ ew, int E) {
    int e = blockIdx.x * blockDim.x + threadIdx.x;
    if (e < E) {
        int p = atomicAdd(&g_cur[row[e]], 1);
        int2 packed;
        packed.x = col[e];
        packed.y = __float_as_int(ew[e]);
        g_es[p] = packed;
    }
}

// ---------------- tiled fp32 GEMM: C[M,N] = A[M,K] @ W[K,N] ------------------
template <int K, int N, int TN>
__global__ __launch_bounds__(256)
void gemm_kernel(const float* __restrict__ A, const float* __restrict__ W,
                 float* __restrict__ C, int M) {
    constexpr int BM = 64, BK = 32, TM = 4;
    __shared__ float As[BK][BM + 1];
    __shared__ float Ws[BK][N];

    const int t  = threadIdx.x;
    const int tx = t % 16;
    const int ty = t / 16;
    const int m0 = blockIdx.x * BM;

    float acc[TM][TN];
#pragma unroll
    for (int i = 0; i < TM; i++)
#pragma unroll
        for (int j = 0; j < TN; j++) acc[i][j] = 0.f;

    for (int kk = 0; kk < K; kk += BK) {
#pragma unroll
        for (int r = 0; r < (BM * BK) / 256; r++) {
            int i = t + r * 256;
            int m = i >> 5;
            int k = i & 31;
            float v = 0.f;
            if (m0 + m < M) v = A[(size_t)(m0 + m) * K + kk + k];
            As[k][m] = v;
        }
#pragma unroll
        for (int r = 0; r < (BK * N) / 256; r++) {
            int i = t + r * 256;
            int k = i / N;
            int j = i % N;
            Ws[k][j] = W[(size_t)(kk + k) * N + j];
        }
        __syncthreads();

#pragma unroll
        for (int k = 0; k < BK; k++) {
            float a[TM], b[TN];
#pragma unroll
            for (int i = 0; i < TM; i++) a[i] = As[k][ty * TM + i];
#pragma unroll
            for (int j = 0; j < TN; j++) b[j] = Ws[k][tx * TN + j];
#pragma unroll
            for (int i = 0; i < TM; i++)
#pragma unroll
                for (int j = 0; j < TN; j++) acc[i][j] += a[i] * b[j];
        }
        __syncthreads();
    }

#pragma unroll
    for (int i = 0; i < TM; i++) {
        int m = m0 + ty * TM + i;
        if (m < M) {
#pragma unroll
            for (int j = 0; j < TN; j++)
                C[(size_t)m * N + tx * TN + j] = acc[i][j];
        }
    }
}

// ---------------- CSR SpMM layer 1: h1 = selu(sum_e w*sup[col] + b1) --------
// CH = 24 float4 chunks per node; 24 threads per node.
__global__ __launch_bounds__(192)
void spmm1_kernel(const float* __restrict__ b1) {
    constexpr int CH = NHID / 4;
    int idx = blockIdx.x * 192 + threadIdx.x;
    int n = idx / CH;
    int c = idx - n * CH;
    if (n >= N_NODES) return;
    int off = g_off[n];
    int deg = g_cnt[n];
    const float4* sup = reinterpret_cast<const float4*>(g_support1);

    float4 acc = make_float4(0.f, 0.f, 0.f, 0.f);
    int j = 0;
    for (; j + 1 < deg; j += 2) {
        int2 e0 = g_es[off + j];
        int2 e1 = g_es[off + j + 1];
        float w0 = __int_as_float(e0.y);
        float w1 = __int_as_float(e1.y);
        float4 v0 = sup[(size_t)e0.x * CH + c];
        float4 v1 = sup[(size_t)e1.x * CH + c];
        acc.x += w0 * v0.x + w1 * v1.x;
        acc.y += w0 * v0.y + w1 * v1.y;
        acc.z += w0 * v0.z + w1 * v1.z;
        acc.w += w0 * v0.w + w1 * v1.w;
    }
    if (j < deg) {
        int2 e0 = g_es[off + j];
        float w0 = __int_as_float(e0.y);
        float4 v0 = sup[(size_t)e0.x * CH + c];
        acc.x += w0 * v0.x;
        acc.y += w0 * v0.y;
        acc.z += w0 * v0.z;
        acc.w += w0 * v0.w;
    }
    float4 bb = reinterpret_cast<const float4*>(b1)[c];
    float4 r;
    r.x = selu_f(acc.x + bb.x);
    r.y = selu_f(acc.y + bb.y);
    r.z = selu_f(acc.z + bb.z);
    r.w = selu_f(acc.w + bb.w);
    reinterpret_cast<float4*>(g_h1)[(size_t)n * CH + c] = r;
}

// ---------------- CSR SpMM layer 2 fused with selu + mean-pool ---------------
// 16 float4 chunks per node; 16 threads per node, 16 nodes per 256-thr block.
// h2 = selu(agg2 + b2) is reduced straight into g_pool (never materialized).
__global__ __launch_bounds__(256)
void spmm2_pool_kernel(const float* __restrict__ b2) {
    constexpr int CH = NCLASS / 4;
    __shared__ float sp[NCLASS];
    int t = threadIdx.x;
    if (t < NCLASS) sp[t] = 0.f;
    __syncthreads();

    int idx = blockIdx.x * 256 + t;
    int n = idx / CH;
    int c = idx - n * CH;
    float4 r = make_float4(0.f, 0.f, 0.f, 0.f);

    if (n < N_NODES) {
        int off = g_off[n];
        int deg = g_cnt[n];
        const float4* sup = reinterpret_cast<const float4*>(g_support2);
        float4 acc = make_float4(0.f, 0.f, 0.f, 0.f);
        int j = 0;
        for (; j + 1 < deg; j += 2) {
            int2 e0 = g_es[off + j];
            int2 e1 = g_es[off + j + 1];
            float w0 = __int_as_float(e0.y);
            float w1 = __int_as_float(e1.y);
            float4 v0 = sup[(size_t)e0.x * CH + c];
            float4 v1 = sup[(size_t)e1.x * CH + c];
            acc.x += w0 * v0.x + w1 * v1.x;
            acc.y += w0 * v0.y + w1 * v1.y;
            acc.z += w0 * v0.z + w1 * v1.z;
            acc.w += w0 * v0.w + w1 * v1.w;
        }
        if (j < deg) {
            int2 e0 = g_es[off + j];
            float w0 = __int_as_float(e0.y);
            float4 v0 = sup[(size_t)e0.x * CH + c];
            acc.x += w0 * v0.x;
            acc.y += w0 * v0.y;
            acc.z += w0 * v0.z;
            acc.w += w0 * v0.w;
        }
        float4 bb = reinterpret_cast<const float4*>(b2)[c];
        r.x = selu_f(acc.x + bb.x);
        r.y = selu_f(acc.y + bb.y);
        r.z = selu_f(acc.z + bb.z);
        r.w = selu_f(acc.w + bb.w);
    }

    // lanes t and t^16 share the same chunk c (different nodes): pairwise sum
    r.x += __shfl_xor_sync(0xffffffffu, r.x, 16);
    r.y += __shfl_xor_sync(0xffffffffu, r.y, 16);
    r.z += __shfl_xor_sync(0xffffffffu, r.z, 16);
    r.w += __shfl_xor_sync(0xffffffffu, r.w, 16);
    if ((t & 16) == 0) {
        atomicAdd(&sp[c * 4 + 0], r.x);
        atomicAdd(&sp[c * 4 + 1], r.y);
        atomicAdd(&sp[c * 4 + 2], r.z);
        atomicAdd(&sp[c * 4 + 3], r.w);
    }
    __syncthreads();
    if (t < NCLASS) atomicAdd(&g_pool[t], sp[t]);
}

// ---------------- final head: BN, concat, FC, log-softmax, L1 ----------------
__global__ __launch_bounds__(128)
void final_kernel(const float* __restrict__ sub, const float* __restrict__ Wf,
                  const float* __restrict__ bf, const float* __restrict__ gamma,
                  const float* __restrict__ beta, const float* __restrict__ mean,
                  const float* __restrict__ var, float* __restrict__ out) {
    __shared__ float z[NCLASS + NEXT];
    __shared__ float logits[NCLASS];
    __shared__ float red[128];
    __shared__ float s_max, s_lse;
    int t = threadIdx.x;

    if (t < NCLASS) {
        z[t] = selu_f(g_pool[t] / (float)N_NODES);
    } else if (t < NCLASS + NEXT) {
        int j = t - NCLASS;
        z[t] = (sub[j] - mean[j]) * rsqrtf(var[j] + BN_EPS) * gamma[j] + beta[j];
    }
    __syncthreads();

    if (t < NCLASS) {
        float a = bf[t];
        const float* wrow = Wf + (size_t)t * (NCLASS + NEXT);
#pragma unroll
        for (int k = 0; k < NCLASS + NEXT; k++) a += z[k] * wrow[k];
        logits[t] = a;
    }
    __syncthreads();

    if (t == 0) {
        float m = -INFINITY;
        for (int k = 0; k < NCLASS; k++) m = fmaxf(m, logits[k]);
        float s = 0.f;
        for (int k = 0; k < NCLASS; k++) s += expf(logits[k] - m);
        s_max = m;
        s_lse = logf(s);
    }
    __syncthreads();
    if (t < NCLASS) out[t] = logits[t] - s_max - s_lse;

    float l = 0.f;
    const int TOTW = NCLASS * (NCLASS + NEXT);
    for (int i = t; i < TOTW; i += 128) l += fabsf(Wf[i]);
    red[t] = l;
    __syncthreads();
    for (int s2 = 64; s2 > 0; s2 >>= 1) {
        if (t < s2) red[t] += red[t + s2];
        __syncthreads();
    }
    if (t == 0) out[NCLASS] = red[0] / (float)TOTW;
}

// ---------------- launch -----------------------------------------------------
extern "C" void kernel_launch(void* const* d_in, const int* in_sizes, int n_in,
                              void* d_out, int out_size) {
    const float* x     = (const float*)d_in[0];
    const int*   row   = (const int*)  d_in[1];
    const int*   col   = (const int*)  d_in[2];
    const float* ew    = (const float*)d_in[3];
    const float* sub   = (const float*)d_in[4];
    const float* W1    = (const float*)d_in[5];
    const float* b1    = (const float*)d_in[6];
    const float* W2    = (const float*)d_in[7];
    const float* b2    = (const float*)d_in[8];
    const float* Wf    = (const float*)d_in[9];
    const float* bf    = (const float*)d_in[10];
    const float* gamma = (const float*)d_in[11];
    const float* beta  = (const float*)d_in[12];
    const float* mean  = (const float*)d_in[13];
    const float* var   = (const float*)d_in[14];
    float* out = (float*)d_out;

    const int M = N_NODES;
    const int E = (n_in > 1) ? in_sizes[1] : N_EDGES;

    void *p_sup1, *p_h1, *p_sup2;
    cudaGetSymbolAddress(&p_sup1, g_support1);
    cudaGetSymbolAddress(&p_h1,   g_h1);
    cudaGetSymbolAddress(&p_sup2, g_support2);

    // ---- CSR build (shared by both layers) ----
    zero_small_kernel<<<(N_NODES + 255) / 256, 256>>>();
    hist_kernel<<<(E + 255) / 256, 256>>>(row, E);
    scanA_kernel<<<NB_SCAN, SCAN_B>>>();
    scanTop_kernel<<<1, 128>>>();
    scanC_kernel<<<(N_NODES + 255) / 256, 256>>>();
    scatter_kernel<<<(E + 255) / 256, 256>>>(row, col, ew, E);

    // ---- layer 1 ----
    gemm_kernel<NFEAT, NHID, 6><<<(M + 63) / 64, 256>>>(x, W1, (float*)p_sup1, M);
    spmm1_kernel<<<(N_NODES * (NHID / 4) + 191) / 192, 192>>>(b1);

    // ---- layer 2 ----
    gemm_kernel<NHID, NCLASS, 4><<<(M + 63) / 64, 256>>>((const float*)p_h1, W2,
                                                         (float*)p_sup2, M);
    spmm2_pool_kernel<<<(N_NODES * (NCLASS / 4) + 255) / 256, 256>>>(b2);

    // ---- head ----
    final_kernel<<<1, 128>>>(sub, Wf, bf, gamma, beta, mean, var, out);
}

// round 4
// speedup vs baseline: 1.3094x; 1.0151x over previous
#include <cuda_runtime.h>
#include <cuda_bf16.h>
#include <math.h>

#define N_NODES 50000
#define N_EDGES 800000
#define NFEAT 128
#define NHID 96
#define NCLASS 64
#define NEXT 32
#define BN_EPS 1e-5f

#define SCAN_B 512
#define NB_SCAN ((N_NODES + SCAN_B - 1) / SCAN_B)   // 98

// ---------------- scratch (device globals; zero-initialized at load) --------
// Invariant maintained by every call: g_cnt == 0, g_pool == 0, g_done == 0 at
// entry and at exit (self-restoring; zero-init covers the first call).
__device__ float g_support1[N_NODES * NHID];
__device__ float g_h1[N_NODES * NHID];
__device__ float g_support2[N_NODES * NCLASS];
__device__ float g_pool[NCLASS];
__device__ int   g_done;

__device__ int  g_cnt[N_NODES];
__device__ int  g_off[N_NODES + 1];
__device__ int  g_cur[N_NODES];
__device__ int  g_partial[NB_SCAN];
__device__ int2 g_es[N_EDGES];

// ---------------- helpers ----------------------------------------------------
__device__ __forceinline__ float selu_f(float v) {
    const float scale = 1.0507009873554805f;
    const float alpha = 1.6732632423543772f;
    return scale * (v > 0.0f ? v : alpha * (expf(v) - 1.0f));
}

// ---------------- K1: histogram (g_cnt starts at 0 by invariant) -------------
__global__ void hist_kernel(const int* __restrict__ row, int E) {
    int e = blockIdx.x * blockDim.x + threadIdx.x;
    if (e < E) atomicAdd(&g_cnt[row[e]], 1);
}

// ---------------- K2: per-block exclusive scan of degrees --------------------
__global__ __launch_bounds__(SCAN_B)
void scanA_kernel() {
    __shared__ int s[SCAN_B];
    int t = threadIdx.x, b = blockIdx.x;
    int i = b * SCAN_B + t;
    int v = (i < N_NODES) ? g_cnt[i] : 0;
    s[t] = v;
    __syncthreads();
    for (int d = 1; d < SCAN_B; d <<= 1) {
        int x = (t >= d) ? s[t - d] : 0;
        __syncthreads();
        s[t] += x;
        __syncthreads();
    }
    if (i < N_NODES) g_off[i] = s[t] - v;
    if (t == SCAN_B - 1) g_partial[b] = s[t];
}

// ---------------- K3: apply top-level scan + init cursors (merged) -----------
__global__ __launch_bounds__(256)
void scanBC_kernel() {
    __shared__ int p[128];
    int t = threadIdx.x;
    p[t & 127] = 0;
    __syncthreads();
    if (t < NB_SCAN) p[t] = g_partial[t];
    __syncthreads();
    // inclusive scan over 128 (covers NB_SCAN=98)
    for (int d = 1; d < 128; d <<= 1) {
        int x = (t < 128 && t >= d) ? p[t - d] : 0;
        __syncthreads();
        if (t < 128) p[t] += x;
        __syncthreads();
    }
    int i = blockIdx.x * 256 + t;
    if (i < N_NODES) {
        int s = i >> 9;  // /SCAN_B
        int base = (s == 0) ? 0 : p[s - 1];
        int o = g_off[i] + base;
        g_off[i] = o;
        g_cur[i] = o;
    }
    if (blockIdx.x == 0 && t == 0) g_off[N_NODES] = p[NB_SCAN - 1];
}

// ---------------- GEMM tile (BM=128, BK=32, 256 thr, 8xTN microtile) ---------
template <int K, int N, int TN>
__device__ __forceinline__
void gemm_tile(const float* __restrict__ A, const float* __restrict__ W,
               float* __restrict__ C, int M, int m0, int t,
               float As[32][129], float Ws[32][N]) {
    constexpr int BM = 128, BK = 32, TM = 8;
    const int tx = t % 16;
    const int ty = t / 16;

    float acc[TM][TN];
#pragma unroll
    for (int i = 0; i < TM; i++)
#pragma unroll
        for (int j = 0; j < TN; j++) acc[i][j] = 0.f;

    for (int kk = 0; kk < K; kk += BK) {
#pragma unroll
        for (int r = 0; r < (BM * BK) / 256; r++) {
            int i = t + r * 256;
            int m = i >> 5;
            int k = i & 31;
            float v = 0.f;
            if (m0 + m < M) v = A[(size_t)(m0 + m) * K + kk + k];
            As[k][m] = v;
        }
#pragma unroll
        for (int r = 0; r < (BK * N) / 256; r++) {
            int i = t + r * 256;
            int k = i / N;
            int j = i % N;
            Ws[k][j] = W[(size_t)(kk + k) * N + j];
        }
        __syncthreads();

#pragma unroll
        for (int k = 0; k < BK; k++) {
            float a[TM], b[TN];
#pragma unroll
            for (int i = 0; i < TM; i++) a[i] = As[k][ty * TM + i];
#pragma unroll
            for (int j = 0; j < TN; j++) b[j] = Ws[k][tx * TN + j];
#pragma unroll
            for (int i = 0; i < TM; i++)
#pragma unroll
                for (int j = 0; j < TN; j++) acc[i][j] += a[i] * b[j];
        }
        __syncthreads();
    }

#pragma unroll
    for (int i = 0; i < TM; i++) {
        int m = m0 + ty * TM + i;
        if (m < M) {
#pragma unroll
            for (int j = 0; j < TN; j++)
                C[(size_t)m * N + tx * TN + j] = acc[i][j];
        }
    }
}

// ---------------- K4: fat kernel — gemm1 || scatter || zero g_cnt ------------
__global__ __launch_bounds__(256)
void fat1_kernel(const float* __restrict__ x, const float* __restrict__ W1,
                 const int* __restrict__ row, const int* __restrict__ col,
                 const float* __restrict__ ew, int E, int GB, int SCB) {
    __shared__ float As[32][129];
    __shared__ float Ws[32][96];
    int bid = blockIdx.x;
    int t = threadIdx.x;

    if (bid < GB) {
        gemm_tile<NFEAT, NHID, 6>(x, W1, g_support1, N_NODES, bid * 128, t, As, Ws);
    } else if (bid < GB + SCB) {
        int base = ((bid - GB) * 256 + t) * 4;
#pragma unroll
        for (int u = 0; u < 4; u++) {
            int e = base + u;
            if (e < E) {
                int p = atomicAdd(&g_cur[row[e]], 1);
                int2 packed;
                packed.x = col[e];
                packed.y = __float_as_int(ew[e]);
                g_es[p] = packed;
            }
        }
    } else {
        // restore invariant: g_cnt = 0 (last reader was scanA)
        int base = ((bid - GB - SCB) * 256 + t) * 4;
#pragma unroll
        for (int u = 0; u < 4; u++) {
            int i = base + u;
            if (i < N_NODES) g_cnt[i] = 0;
        }
    }
}

// ---------------- K5: CSR SpMM layer 1 + bias + SELU -------------------------
__global__ __launch_bounds__(192)
void spmm1_kernel(const float* __restrict__ b1) {
    constexpr int CH = NHID / 4;
    int idx = blockIdx.x * 192 + threadIdx.x;
    int n = idx / CH;
    int c = idx - n * CH;
    if (n >= N_NODES) return;
    int off = g_off[n];
    int deg = g_off[n + 1] - off;
    const float4* sup = reinterpret_cast<const float4*>(g_support1);

    float4 acc = make_float4(0.f, 0.f, 0.f, 0.f);
    int j = 0;
    for (; j + 3 < deg; j += 4) {
        int2 e0 = g_es[off + j];
        int2 e1 = g_es[off + j + 1];
        int2 e2 = g_es[off + j + 2];
        int2 e3 = g_es[off + j + 3];
        float4 v0 = sup[(size_t)e0.x * CH + c];
        float4 v1 = sup[(size_t)e1.x * CH + c];
        float4 v2 = sup[(size_t)e2.x * CH + c];
        float4 v3 = sup[(size_t)e3.x * CH + c];
        float w0 = __int_as_float(e0.y), w1 = __int_as_float(e1.y);
        float w2 = __int_as_float(e2.y), w3 = __int_as_float(e3.y);
        acc.x += w0 * v0.x + w1 * v1.x + w2 * v2.x + w3 * v3.x;
        acc.y += w0 * v0.y + w1 * v1.y + w2 * v2.y + w3 * v3.y;
        acc.z += w0 * v0.z + w1 * v1.z + w2 * v2.z + w3 * v3.z;
        acc.w += w0 * v0.w + w1 * v1.w + w2 * v2.w + w3 * v3.w;
    }
    for (; j < deg; j++) {
        int2 e0 = g_es[off + j];
        float w0 = __int_as_float(e0.y);
        float4 v0 = sup[(size_t)e0.x * CH + c];
        acc.x += w0 * v0.x;
        acc.y += w0 * v0.y;
        acc.z += w0 * v0.z;
        acc.w += w0 * v0.w;
    }
    float4 bb = reinterpret_cast<const float4*>(b1)[c];
    float4 r;
    r.x = selu_f(acc.x + bb.x);
    r.y = selu_f(acc.y + bb.y);
    r.z = selu_f(acc.z + bb.z);
    r.w = selu_f(acc.w + bb.w);
    reinterpret_cast<float4*>(g_h1)[(size_t)n * CH + c] = r;
}

// ---------------- K6: GEMM layer 2 -------------------------------------------
__global__ __launch_bounds__(256)
void gemm2_kernel(const float* __restrict__ W2) {
    __shared__ float As[32][129];
    __shared__ float Ws[32][64];
    gemm_tile<NHID, NCLASS, 4>(g_h1, W2, g_support2, N_NODES,
                               blockIdx.x * 128, threadIdx.x, As, Ws);
}

// ---------------- K7: SpMM layer 2 + selu + pool + (tail block) final head ---
__global__ __launch_bounds__(256)
void spmm2_final_kernel(const float* __restrict__ b2,
                        const float* __restrict__ sub, const float* __restrict__ Wf,
                        const float* __restrict__ bf, const float* __restrict__ gamma,
                        const float* __restrict__ beta, const float* __restrict__ mean,
                        const float* __restrict__ var, float* __restrict__ out) {
    constexpr int CH = NCLASS / 4;
    __shared__ float sp[NCLASS];
    __shared__ int s_last;
    int t = threadIdx.x;
    if (t < NCLASS) sp[t] = 0.f;
    __syncthreads();

    int idx = blockIdx.x * 256 + t;
    int n = idx / CH;
    int c = idx - n * CH;
    float4 r = make_float4(0.f, 0.f, 0.f, 0.f);

    if (n < N_NODES) {
        int off = g_off[n];
        int deg = g_off[n + 1] - off;
        const float4* sup = reinterpret_cast<const float4*>(g_support2);
        float4 acc = make_float4(0.f, 0.f, 0.f, 0.f);
        int j = 0;
        for (; j + 3 < deg; j += 4) {
            int2 e0 = g_es[off + j];
            int2 e1 = g_es[off + j + 1];
            int2 e2 = g_es[off + j + 2];
            int2 e3 = g_es[off + j + 3];
            float4 v0 = sup[(size_t)e0.x * CH + c];
            float4 v1 = sup[(size_t)e1.x * CH + c];
            float4 v2 = sup[(size_t)e2.x * CH + c];
            float4 v3 = sup[(size_t)e3.x * CH + c];
            float w0 = __int_as_float(e0.y), w1 = __int_as_float(e1.y);
            float w2 = __int_as_float(e2.y), w3 = __int_as_float(e3.y);
            acc.x += w0 * v0.x + w1 * v1.x + w2 * v2.x + w3 * v3.x;
            acc.y += w0 * v0.y + w1 * v1.y + w2 * v2.y + w3 * v3.y;
            acc.z += w0 * v0.z + w1 * v1.z + w2 * v2.z + w3 * v3.z;
            acc.w += w0 * v0.w + w1 * v1.w + w2 * v2.w + w3 * v3.w;
        }
        for (; j < deg; j++) {
            int2 e0 = g_es[off + j];
            float w0 = __int_as_float(e0.y);
            float4 v0 = sup[(size_t)e0.x * CH + c];
            acc.x += w0 * v0.x;
            acc.y += w0 * v0.y;
            acc.z += w0 * v0.z;
            acc.w += w0 * v0.w;
        }
        float4 bb = reinterpret_cast<const float4*>(b2)[c];
        r.x = selu_f(acc.x + bb.x);
        r.y = selu_f(acc.y + bb.y);
        r.z = selu_f(acc.z + bb.z);
        r.w = selu_f(acc.w + bb.w);
    }

    // lanes t and t^16 share chunk c (different nodes)
    r.x += __shfl_xor_sync(0xffffffffu, r.x, 16);
    r.y += __shfl_xor_sync(0xffffffffu, r.y, 16);
    r.z += __shfl_xor_sync(0xffffffffu, r.z, 16);
    r.w += __shfl_xor_sync(0xffffffffu, r.w, 16);
    if ((t & 16) == 0) {
        atomicAdd(&sp[c * 4 + 0], r.x);
        atomicAdd(&sp[c * 4 + 1], r.y);
        atomicAdd(&sp[c * 4 + 2], r.z);
        atomicAdd(&sp[c * 4 + 3], r.w);
    }
    __syncthreads();
    if (t < NCLASS) atomicAdd(&g_pool[t], sp[t]);

    // ---- tail-block election ----
    __threadfence();
    __syncthreads();
    if (t == 0) s_last = (atomicAdd(&g_done, 1) == (int)gridDim.x - 1);
    __syncthreads();
    if (!s_last) return;
    __threadfence();

    // ---- final head (runs in exactly one block, after all pool atomics) ----
    __shared__ float z[NCLASS + NEXT];
    __shared__ float logits[NCLASS];
    __shared__ float red[256];
    __shared__ float s_max, s_lse;

    if (t < NCLASS) {
        z[t] = selu_f(__ldcg(&g_pool[t]) / (float)N_NODES);
    } else if (t < NCLASS + NEXT) {
        int jj = t - NCLASS;
        z[t] = (sub[jj] - mean[jj]) * rsqrtf(var[jj] + BN_EPS) * gamma[jj] + beta[jj];
    }
    __syncthreads();

    if (t < NCLASS) {
        float a = bf[t];
        const float* wrow = Wf + (size_t)t * (NCLASS + NEXT);
#pragma unroll
        for (int k = 0; k < NCLASS + NEXT; k++) a += z[k] * wrow[k];
        logits[t] = a;
    }
    __syncthreads();

    if (t == 0) {
        float m = -INFINITY;
        for (int k = 0; k < NCLASS; k++) m = fmaxf(m, logits[k]);
        float s = 0.f;
        for (int k = 0; k < NCLASS; k++) s += expf(logits[k] - m);
        s_max = m;
        s_lse = logf(s);
    }
    __syncthreads();
    if (t < NCLASS) out[t] = logits[t] - s_max - s_lse;

    float l = 0.f;
    const int TOTW = NCLASS * (NCLASS + NEXT);
    for (int i = t; i < TOTW; i += 256) l += fabsf(Wf[i]);
    red[t] = l;
    __syncthreads();
    for (int s2 = 128; s2 > 0; s2 >>= 1) {
        if (t < s2) red[t] += red[t + s2];
        __syncthreads();
    }
    if (t == 0) out[NCLASS] = red[0] / (float)TOTW;

    // restore invariants
    if (t < NCLASS) g_pool[t] = 0.f;
    if (t == 0) g_done = 0;
}

// ---------------- launch -----------------------------------------------------
extern "C" void kernel_launch(void* const* d_in, const int* in_sizes, int n_in,
                              void* d_out, int out_size) {
    const float* x     = (const float*)d_in[0];
    const int*   row   = (const int*)  d_in[1];
    const int*   col   = (const int*)  d_in[2];
    const float* ew    = (const float*)d_in[3];
    const float* sub   = (const float*)d_in[4];
    const float* W1    = (const float*)d_in[5];
    const float* b1    = (const float*)d_in[6];
    const float* W2    = (const float*)d_in[7];
    const float* b2    = (const float*)d_in[8];
    const float* Wf    = (const float*)d_in[9];
    const float* bf    = (const float*)d_in[10];
    const float* gamma = (const float*)d_in[11];
    const float* beta  = (const float*)d_in[12];
    const float* mean  = (const float*)d_in[13];
    const float* var   = (const float*)d_in[14];
    float* out = (float*)d_out;

    const int E = (n_in > 1) ? in_sizes[1] : N_EDGES;

    const int GB  = (N_NODES + 127) / 128;             // gemm1 blocks
    const int SCB = (E + 1023) / 1024;                 // scatter blocks (4 e/thr)
    const int ZB  = (N_NODES + 1023) / 1024;           // g_cnt zero blocks

    // K1-K3: CSR build
    hist_kernel<<<(E + 255) / 256, 256>>>(row, E);
    scanA_kernel<<<NB_SCAN, SCAN_B>>>();
    scanBC_kernel<<<(N_NODES + 255) / 256, 256>>>();
    // K4: gemm1 || scatter || zero g_cnt
    fat1_kernel<<<GB + SCB + ZB, 256>>>(x, W1, row, col, ew, E, GB, SCB);
    // K5: spmm1 (+bias+selu)
    spmm1_kernel<<<(N_NODES * (NHID / 4) + 191) / 192, 192>>>(b1);
    // K6: gemm2
    gemm2_kernel<<<GB, 256>>>(W2);
    // K7: spmm2 + pool + final head (tail block)
    spmm2_final_kernel<<<(N_NODES * (NCLASS / 4) + 255) / 256, 256>>>(
        b2, sub, Wf, bf, gamma, beta, mean, var, out);
}

// round 6
// speedup vs baseline: 1.6802x; 1.2832x over previous
#include <cuda_runtime.h>
#include <cuda_bf16.h>
#include <math.h>

#define N_NODES 50000
#define N_EDGES 800000
#define NFEAT 128
#define NHID 96
#define NCLASS 64
#define NEXT 32
#define BN_EPS 1e-5f

#define SCAN_B 512
#define NB_SCAN ((N_NODES + SCAN_B - 1) / SCAN_B)   // 98

// ---------------- scratch (device globals; zero-initialized at load) --------
// Invariant at entry/exit of every call: g_cnt == 0, g_pool == 0, g_done == 0.
__device__ float g_support1[N_NODES * NHID];
__device__ float g_h1[N_NODES * NHID];
__device__ float g_support2[N_NODES * NCLASS];
__device__ float g_pool[NCLASS];
__device__ int   g_done;

__device__ int  g_cnt[N_NODES];
__device__ int  g_off[N_NODES + 1];
__device__ int  g_cur[N_NODES];
__device__ int  g_partial[NB_SCAN];
__device__ int2 g_es[N_EDGES];

// ---------------- helpers ----------------------------------------------------
__device__ __forceinline__ float selu_f(float v) {
    const float scale = 1.0507009873554805f;
    const float alpha = 1.6732632423543772f;
    return scale * (v > 0.0f ? v : alpha * (expf(v) - 1.0f));
}

__device__ __forceinline__ unsigned f2tf32(float f) {
    unsigned u;
    asm("cvt.rna.tf32.f32 %0, %1;" : "=r"(u) : "f"(f));
    return u;
}

__device__ __forceinline__ void mma_tf32(float c[4], const unsigned a[4],
                                         const unsigned b[2]) {
    asm volatile(
        "mma.sync.aligned.m16n8k8.row.col.f32.tf32.tf32.f32 "
        "{%0,%1,%2,%3}, {%4,%5,%6,%7}, {%8,%9}, {%0,%1,%2,%3};"
        : "+f"(c[0]), "+f"(c[1]), "+f"(c[2]), "+f"(c[3])
        : "r"(a[0]), "r"(a[1]), "r"(a[2]), "r"(a[3]), "r"(b[0]), "r"(b[1]));
}

// ---------------- K1: histogram ----------------------------------------------
__global__ void hist_kernel(const int* __restrict__ row, int E) {
    int e = blockIdx.x * blockDim.x + threadIdx.x;
    if (e < E) atomicAdd(&g_cnt[row[e]], 1);
}

// ---------------- K2: per-block exclusive scan of degrees --------------------
__global__ __launch_bounds__(SCAN_B)
void scanA_kernel() {
    __shared__ int s[SCAN_B];
    int t = threadIdx.x, b = blockIdx.x;
    int i = b * SCAN_B + t;
    int v = (i < N_NODES) ? g_cnt[i] : 0;
    s[t] = v;
    __syncthreads();
    for (int d = 1; d < SCAN_B; d <<= 1) {
        int x = (t >= d) ? s[t - d] : 0;
        __syncthreads();
        s[t] += x;
        __syncthreads();
    }
    if (i < N_NODES) g_off[i] = s[t] - v;
    if (t == SCAN_B - 1) g_partial[b] = s[t];
}

// ---------------- K3: apply top-level scan + init cursors --------------------
__global__ __launch_bounds__(256)
void scanBC_kernel() {
    __shared__ int p[128];
    int t = threadIdx.x;
    p[t & 127] = 0;
    __syncthreads();
    if (t < NB_SCAN) p[t] = g_partial[t];
    __syncthreads();
    for (int d = 1; d < 128; d <<= 1) {
        int x = (t < 128 && t >= d) ? p[t - d] : 0;
        __syncthreads();
        if (t < 128) p[t] += x;
        __syncthreads();
    }
    int i = blockIdx.x * 256 + t;
    if (i < N_NODES) {
        int s = i >> 9;
        int base = (s == 0) ? 0 : p[s - 1];
        int o = g_off[i] + base;
        g_off[i] = o;
        g_cur[i] = o;
    }
    if (blockIdx.x == 0 && t == 0) g_off[N_NODES] = p[NB_SCAN - 1];
}

// ---------------- tf32 tensor-core GEMM tile ---------------------------------
// C[M,N] = A[M,K] @ W[K,N], row-major. 256 thr = 8 warps as 4(m) x 2(n).
// Block tile: BM=128, BN=N, BK=32. Warp tile: 32 x (N/2). NT = N/16 mma n-tiles.
// SMEM: As[32][136] (bank stride 8: conflict-free A frags),
//       Bs[N][36]   (bank stride 4: conflict-free B frags).
template <int K, int N, int NT>
__device__ __forceinline__
void gemm_tf32(const float* __restrict__ A, const float* __restrict__ W,
               float* __restrict__ C, int M, int m0) {
    __shared__ unsigned As[32][136];
    __shared__ unsigned Bs[N][36];

    const int t = threadIdx.x;
    const int lane = t & 31;
    const int wid = t >> 5;
    const int warp_m = wid >> 1;        // 0..3
    const int warp_n = wid & 1;         // 0..1
    const int lq = lane >> 2;           // 0..7
    const int lr = lane & 3;            // 0..3

    float acc[2][NT][4];
#pragma unroll
    for (int i = 0; i < 2; i++)
#pragma unroll
        for (int j = 0; j < NT; j++)
#pragma unroll
            for (int q = 0; q < 4; q++) acc[i][j][q] = 0.f;

    const int arow = t >> 1;            // 0..127 (staging row)
    const int aq0 = (t & 1) * 4;        // float4 quad base

    for (int kk = 0; kk < K; kk += 32) {
        // stage A tile [128 x 32] -> As[k][m], tf32
#pragma unroll
        for (int q = 0; q < 4; q++) {
            int kq = (aq0 + q) * 4;
            float4 v = make_float4(0.f, 0.f, 0.f, 0.f);
            if (m0 + arow < M)
                v = *reinterpret_cast<const float4*>(A + (size_t)(m0 + arow) * K + kk + kq);
            As[kq + 0][arow] = f2tf32(v.x);
            As[kq + 1][arow] = f2tf32(v.y);
            As[kq + 2][arow] = f2tf32(v.z);
            As[kq + 3][arow] = f2tf32(v.w);
        }
        // stage W tile [32 x N] -> Bs[n][k], tf32
        for (int i = t; i < 32 * N; i += 256) {
            int k = i / N;
            int n = i - k * N;
            Bs[n][k] = f2tf32(W[(size_t)(kk + k) * N + n]);
        }
        __syncthreads();

#pragma unroll
        for (int ks = 0; ks < 4; ks++) {
            const int k8 = ks * 8;
            unsigned b[NT][2];
            const int bn = warp_n * (NT * 8) + lq;
#pragma unroll
            for (int j = 0; j < NT; j++) {
                b[j][0] = Bs[bn + j * 8][k8 + lr];
                b[j][1] = Bs[bn + j * 8][k8 + lr + 4];
            }
            unsigned a[2][4];
            const int am = warp_m * 32 + lq;
#pragma unroll
            for (int i = 0; i < 2; i++) {
                int r = am + i * 16;
                a[i][0] = As[k8 + lr][r];
                a[i][1] = As[k8 + lr][r + 8];
                a[i][2] = As[k8 + lr + 4][r];
                a[i][3] = As[k8 + lr + 4][r + 8];
            }
#pragma unroll
            for (int i = 0; i < 2; i++)
#pragma unroll
                for (int j = 0; j < NT; j++) mma_tf32(acc[i][j], a[i], b[j]);
        }
        __syncthreads();
    }

    // epilogue: c0,c1 at (r, 2lr), (r, 2lr+1); c2,c3 at (r+8, ...)
#pragma unroll
    for (int i = 0; i < 2; i++) {
        int r0 = m0 + warp_m * 32 + i * 16 + lq;
#pragma unroll
        for (int j = 0; j < NT; j++) {
            int c0 = warp_n * (NT * 8) + j * 8 + 2 * lr;
            if (r0 < M)
                *reinterpret_cast<float2*>(C + (size_t)r0 * N + c0) =
                    make_float2(acc[i][j][0], acc[i][j][1]);
            if (r0 + 8 < M)
                *reinterpret_cast<float2*>(C + (size_t)(r0 + 8) * N + c0) =
                    make_float2(acc[i][j][2], acc[i][j][3]);
        }
    }
}

// ---------------- K4: fat kernel — gemm1(tf32) || scatter || zero g_cnt ------
__global__ __launch_bounds__(256)
void fat1_kernel(const float* __restrict__ x, const float* __restrict__ W1,
                 const int* __restrict__ row, const int* __restrict__ col,
                 const float* __restrict__ ew, int E, int GB, int SCB) {
    int bid = blockIdx.x;
    int t = threadIdx.x;

    if (bid < GB) {
        gemm_tf32<NFEAT, NHID, 6>(x, W1, g_support1, N_NODES, bid * 128);
    } else if (bid < GB + SCB) {
        int base = ((bid - GB) * 256 + t) * 4;
#pragma unroll
        for (int u = 0; u < 4; u++) {
            int e = base + u;
            if (e < E) {
                int p = atomicAdd(&g_cur[row[e]], 1);
                int2 packed;
                packed.x = col[e];
                packed.y = __float_as_int(ew[e]);
                g_es[p] = packed;
            }
        }
    } else {
        int base = ((bid - GB - SCB) * 256 + t) * 4;
#pragma unroll
        for (int u = 0; u < 4; u++) {
            int i = base + u;
            if (i < N_NODES) g_cnt[i] = 0;
        }
    }
}

// ---------------- K5: CSR SpMM layer 1 + bias + SELU -------------------------
__global__ __launch_bounds__(192)
void spmm1_kernel(const float* __restrict__ b1) {
    constexpr int CH = NHID / 4;
    int idx = blockIdx.x * 192 + threadIdx.x;
    int n = idx / CH;
    int c = idx - n * CH;
    if (n >= N_NODES) return;
    int off = g_off[n];
    int deg = g_off[n + 1] - off;
    const float4* sup = reinterpret_cast<const float4*>(g_support1);

    float4 acc = make_float4(0.f, 0.f, 0.f, 0.f);
    int j = 0;
    for (; j + 3 < deg; j += 4) {
        int2 e0 = g_es[off + j];
        int2 e1 = g_es[off + j + 1];
        int2 e2 = g_es[off + j + 2];
        int2 e3 = g_es[off + j + 3];
        float4 v0 = sup[(size_t)e0.x * CH + c];
        float4 v1 = sup[(size_t)e1.x * CH + c];
        float4 v2 = sup[(size_t)e2.x * CH + c];
        float4 v3 = sup[(size_t)e3.x * CH + c];
        float w0 = __int_as_float(e0.y), w1 = __int_as_float(e1.y);
        float w2 = __int_as_float(e2.y), w3 = __int_as_float(e3.y);
        acc.x += w0 * v0.x + w1 * v1.x + w2 * v2.x + w3 * v3.x;
        acc.y += w0 * v0.y + w1 * v1.y + w2 * v2.y + w3 * v3.y;
        acc.z += w0 * v0.z + w1 * v1.z + w2 * v2.z + w3 * v3.z;
        acc.w += w0 * v0.w + w1 * v1.w + w2 * v2.w + w3 * v3.w;
    }
    for (; j < deg; j++) {
        int2 e0 = g_es[off + j];
        float w0 = __int_as_float(e0.y);
        float4 v0 = sup[(size_t)e0.x * CH + c];
        acc.x += w0 * v0.x;
        acc.y += w0 * v0.y;
        acc.z += w0 * v0.z;
        acc.w += w0 * v0.w;
    }
    float4 bb = reinterpret_cast<const float4*>(b1)[c];
    float4 r;
    r.x = selu_f(acc.x + bb.x);
    r.y = selu_f(acc.y + bb.y);
    r.z = selu_f(acc.z + bb.z);
    r.w = selu_f(acc.w + bb.w);
    reinterpret_cast<float4*>(g_h1)[(size_t)n * CH + c] = r;
}

// ---------------- K6: GEMM layer 2 (tf32) ------------------------------------
__global__ __launch_bounds__(256)
void gemm2_kernel(const float* __restrict__ W2) {
    gemm_tf32<NHID, NCLASS, 4>(g_h1, W2, g_support2, N_NODES, blockIdx.x * 128);
}

// ---------------- K7: SpMM layer 2 + selu + pool + tail-block head -----------
__global__ __launch_bounds__(256)
void spmm2_final_kernel(const float* __restrict__ b2,
                        const float* __restrict__ sub, const float* __restrict__ Wf,
                        const float* __restrict__ bf, const float* __restrict__ gamma,
                        const float* __restrict__ beta, const float* __restrict__ mean,
                        const float* __restrict__ var, float* __restrict__ out) {
    constexpr int CH = NCLASS / 4;
    __shared__ float sp[NCLASS];
    __shared__ int s_last;
    int t = threadIdx.x;
    if (t < NCLASS) sp[t] = 0.f;
    __syncthreads();

    int idx = blockIdx.x * 256 + t;
    int n = idx / CH;
    int c = idx - n * CH;
    float4 r = make_float4(0.f, 0.f, 0.f, 0.f);

    if (n < N_NODES) {
        int off = g_off[n];
        int deg = g_off[n + 1] - off;
        const float4* sup = reinterpret_cast<const float4*>(g_support2);
        float4 acc = make_float4(0.f, 0.f, 0.f, 0.f);
        int j = 0;
        for (; j + 3 < deg; j += 4) {
            int2 e0 = g_es[off + j];
            int2 e1 = g_es[off + j + 1];
            int2 e2 = g_es[off + j + 2];
            int2 e3 = g_es[off + j + 3];
            float4 v0 = sup[(size_t)e0.x * CH + c];
            float4 v1 = sup[(size_t)e1.x * CH + c];
            float4 v2 = sup[(size_t)e2.x * CH + c];
            float4 v3 = sup[(size_t)e3.x * CH + c];
            float w0 = __int_as_float(e0.y), w1 = __int_as_float(e1.y);
            float w2 = __int_as_float(e2.y), w3 = __int_as_float(e3.y);
            acc.x += w0 * v0.x + w1 * v1.x + w2 * v2.x + w3 * v3.x;
            acc.y += w0 * v0.y + w1 * v1.y + w2 * v2.y + w3 * v3.y;
            acc.z += w0 * v0.z + w1 * v1.z + w2 * v2.z + w3 * v3.z;
            acc.w += w0 * v0.w + w1 * v1.w + w2 * v2.w + w3 * v3.w;
        }
        for (; j < deg; j++) {
            int2 e0 = g_es[off + j];
            float w0 = __int_as_float(e0.y);
            float4 v0 = sup[(size_t)e0.x * CH + c];
            acc.x += w0 * v0.x;
            acc.y += w0 * v0.y;
            acc.z += w0 * v0.z;
            acc.w += w0 * v0.w;
        }
        float4 bb = reinterpret_cast<const float4*>(b2)[c];
        r.x = selu_f(acc.x + bb.x);
        r.y = selu_f(acc.y + bb.y);
        r.z = selu_f(acc.z + bb.z);
        r.w = selu_f(acc.w + bb.w);
    }

    r.x += __shfl_xor_sync(0xffffffffu, r.x, 16);
    r.y += __shfl_xor_sync(0xffffffffu, r.y, 16);
    r.z += __shfl_xor_sync(0xffffffffu, r.z, 16);
    r.w += __shfl_xor_sync(0xffffffffu, r.w, 16);
    if ((t & 16) == 0) {
        atomicAdd(&sp[c * 4 + 0], r.x);
        atomicAdd(&sp[c * 4 + 1], r.y);
        atomicAdd(&sp[c * 4 + 2], r.z);
        atomicAdd(&sp[c * 4 + 3], r.w);
    }
    __syncthreads();
    if (t < NCLASS) atomicAdd(&g_pool[t], sp[t]);

    __threadfence();
    __syncthreads();
    if (t == 0) s_last = (atomicAdd(&g_done, 1) == (int)gridDim.x - 1);
    __syncthreads();
    if (!s_last) return;
    __threadfence();

    __shared__ float z[NCLASS + NEXT];
    __shared__ float logits[NCLASS];
    __shared__ float red[256];
    __shared__ float s_max, s_lse;

    if (t < NCLASS) {
        z[t] = selu_f(__ldcg(&g_pool[t]) / (float)N_NODES);
    } else if (t < NCLASS + NEXT) {
        int jj = t - NCLASS;
        z[t] = (sub[jj] - mean[jj]) * rsqrtf(var[jj] + BN_EPS) * gamma[jj] + beta[jj];
    }
    __syncthreads();

    if (t < NCLASS) {
        float a = bf[t];
        const float* wrow = Wf + (size_t)t * (NCLASS + NEXT);
#pragma unroll
        for (int k = 0; k < NCLASS + NEXT; k++) a += z[k] * wrow[k];
        logits[t] = a;
    }
    __syncthreads();

    if (t == 0) {
        float m = -INFINITY;
        for (int k = 0; k < NCLASS; k++) m = fmaxf(m, logits[k]);
        float s = 0.f;
        for (int k = 0; k < NCLASS; k++) s += expf(logits[k] - m);
        s_max = m;
        s_lse = logf(s);
    }
    __syncthreads();
    if (t < NCLASS) out[t] = logits[t] - s_max - s_lse;

    float l = 0.f;
    const int TOTW = NCLASS * (NCLASS + NEXT);
    for (int i = t; i < TOTW; i += 256) l += fabsf(Wf[i]);
    red[t] = l;
    __syncthreads();
    for (int s2 = 128; s2 > 0; s2 >>= 1) {
        if (t < s2) red[t] += red[t + s2];
        __syncthreads();
    }
    if (t == 0) out[NCLASS] = red[0] / (float)TOTW;

    if (t < NCLASS) g_pool[t] = 0.f;
    if (t == 0) g_done = 0;
}

// ---------------- launch -----------------------------------------------------
extern "C" void kernel_launch(void* const* d_in, const int* in_sizes, int n_in,
                              void* d_out, int out_size) {
    const float* x     = (const float*)d_in[0];
    const int*   row   = (const int*)  d_in[1];
    const int*   col   = (const int*)  d_in[2];
    const float* ew    = (const float*)d_in[3];
    const float* sub   = (const float*)d_in[4];
    const float* W1    = (const float*)d_in[5];
    const float* b1    = (const float*)d_in[6];
    const float* W2    = (const float*)d_in[7];
    const float* b2    = (const float*)d_in[8];
    const float* Wf    = (const float*)d_in[9];
    const float* bf    = (const float*)d_in[10];
    const float* gamma = (const float*)d_in[11];
    const float* beta  = (const float*)d_in[12];
    const float* mean  = (const float*)d_in[13];
    const float* var   = (const float*)d_in[14];
    float* out = (float*)d_out;

    const int E = (n_in > 1) ? in_sizes[1] : N_EDGES;

    const int GB  = (N_NODES + 127) / 128;   // 391 gemm blocks
    const int SCB = (E + 1023) / 1024;       // scatter blocks
    const int ZB  = (N_NODES + 1023) / 1024; // zero blocks

    hist_kernel<<<(E + 255) / 256, 256>>>(row, E);
    scanA_kernel<<<NB_SCAN, SCAN_B>>>();
    scanBC_kernel<<<(N_NODES + 255) / 256, 256>>>();
    fat1_kernel<<<GB + SCB + ZB, 256>>>(x, W1, row, col, ew, E, GB, SCB);
    spmm1_kernel<<<(N_NODES * (NHID / 4) + 191) / 192, 192>>>(b1);
    gemm2_kernel<<<GB, 256>>>(W2);
    spmm2_final_kernel<<<(N_NODES * (NCLASS / 4) + 255) / 256, 256>>>(
        b2, sub, Wf, bf, gamma, beta, mean, var, out);
}